// round 1
// baseline (speedup 1.0000x reference)
#include <cuda_runtime.h>
#include <math.h>

// Problem constants (shapes fixed by the dataset)
#define NB 32
#define NA 3
#define NH 128
#define NW 128
#define NCH (NA * 6)              // 18 channels
#define NPLANE (NH * NW)          // 16384
#define NCELL (NB * NA * NPLANE)  // 1,572,864
#define EPSF 1e-7f

// Self-cleaning scratch (zero-initialized at module load; every launch restores zeros)
__device__ int    d_clr[NCELL];    // cleared-cell dedup flags
__device__ int    d_owner[NCELL];  // winning gt index + 1 per obj cell
__device__ double d_total;         // dense noobj-BCE sum over ALL cells

__constant__ float c_aw[3] = {116.f, 156.f, 373.f};
__constant__ float c_ah[3] = { 90.f, 198.f, 326.f};

// -log(1 - clip(sigmoid(v), eps, 1-eps))   [noobj BCE term]
__device__ __forceinline__ float bce_neg(float v) {
    float s = 1.0f / (1.0f + expf(-v));
    float p = fminf(fmaxf(s, EPSF), 1.0f - EPSF);
    return -logf(1.0f - p);
}
// -log(clip(sigmoid(v), eps, 1-eps))       [obj BCE term]
__device__ __forceinline__ float bce_pos(float v) {
    float s = 1.0f / (1.0f + expf(-v));
    float p = fminf(fmaxf(s, EPSF), 1.0f - EPSF);
    return -logf(p);
}
__device__ __forceinline__ float sigmoidf_(float v) {
    return 1.0f / (1.0f + expf(-v));
}

// ---------------------------------------------------------------------------
// Kernel 1: dense sum of -log(1-p) over the conf channel (a*6+4) of all cells.
// 393,216 float4 elements; exact grid 1536 x 256.
// ---------------------------------------------------------------------------
__global__ void conf_sum_kernel(const float* __restrict__ out) {
    const int tid = threadIdx.x;
    const int idx = blockIdx.x * 256 + tid;            // 0 .. 393215
    const float4* __restrict__ o4 = (const float4*)out;

    const int plane = idx >> 12;                       // 0..95  (b*3 + a)
    const int j     = idx & 4095;
    const int b     = plane / 3;
    const int a     = plane - 3 * b;
    const size_t off = (size_t)(b * NCH + a * 6 + 4) * 4096 + j;
    float4 v = o4[off];

    float s = bce_neg(v.x) + bce_neg(v.y) + bce_neg(v.z) + bce_neg(v.w);

    __shared__ float red[256];
    red[tid] = s;
    __syncthreads();
#pragma unroll
    for (int k = 128; k > 0; k >>= 1) {
        if (tid < k) red[tid] += red[tid + k];
        __syncthreads();
    }
    if (tid == 0) atomicAdd(&d_total, (double)red[0]);
}

// ---------------------------------------------------------------------------
// Kernel 2: single-block tail. Phases:
//   A: per-gt clear/dedup (+ correction sum of noobj terms at cleared cells)
//      and owner atomicMax at the best-anchor cell
//   B: owner winners compute obj BCE + bbox MSE terms
//   C: cleanup (restore d_clr / d_owner to zero at touched cells)
//   D: thread 0 combines everything and writes the scalar; resets d_total
// ---------------------------------------------------------------------------
__global__ void tail_kernel(const float* __restrict__ out,
                            const int*   __restrict__ gt_batch,
                            const float* __restrict__ gt_boxes,
                            const int*   __restrict__ size_h,
                            const int*   __restrict__ size_w,
                            float* __restrict__ d_out,
                            int nGts) {
    const int tid = threadIdx.x;
    const int NT  = blockDim.x;

    const float stride_h = (float)((*size_h) / NH);
    const float stride_w = (float)((*size_w) / NW);
    float awf[3], ahf[3];
#pragma unroll
    for (int a = 0; a < 3; a++) { awf[a] = c_aw[a] / stride_w; ahf[a] = c_ah[a] / stride_h; }

    __shared__ double redD[1024];
    __shared__ int    redI[1024];
    __shared__ double s_corr, s_obj;
    __shared__ int    s_nclr, s_nobj;

    const float4* __restrict__ boxes4 = (const float4*)gt_boxes;

    // ---------------- Phase A ----------------
    double corr = 0.0;
    int nclr = 0;
    for (int g = tid; g < nGts; g += NT) {
        const int b = gt_batch[g];
        float4 box = boxes4[g];
        float gx = box.x * (float)NW, gy = box.y * (float)NH;
        float gw = box.z * (float)NW, gh = box.w * (float)NH;
        int gi = (int)gx, gj = (int)gy;

        float ious[3]; float best = -1.0f; int bestn = 0;
#pragma unroll
        for (int a = 0; a < 3; a++) {
            float inter = fminf(gw, awf[a]) * fminf(gh, ahf[a]);
            float uni   = gw * gh + awf[a] * ahf[a] - inter;
            float iou   = inter / uni;
            ious[a] = iou;
            if (iou > best) { best = iou; bestn = a; }
        }
        const int cellbase = ((b * NA) * NH + gj) * NW + gi;
#pragma unroll
        for (int a = 0; a < 3; a++) {
            bool cleared = (ious[a] > 0.5f) || (a == bestn);
            if (cleared) {
                int cell = cellbase + a * NPLANE;
                if (atomicExch(&d_clr[cell], 1) == 0) {
                    float v = out[(size_t)(b * NCH + a * 6 + 4) * NPLANE + gj * NW + gi];
                    corr += (double)bce_neg(v);
                    nclr++;
                }
            }
        }
        atomicMax(&d_owner[cellbase + bestn * NPLANE], g + 1);
    }
    redD[tid] = corr; redI[tid] = nclr;
    __syncthreads();
    for (int k = NT >> 1; k > 0; k >>= 1) {
        if (tid < k) { redD[tid] += redD[tid + k]; redI[tid] += redI[tid + k]; }
        __syncthreads();
    }
    if (tid == 0) { s_corr = redD[0]; s_nclr = redI[0]; }
    __syncthreads();

    // ---------------- Phase B ----------------
    double objsum = 0.0;
    int nobj = 0;
    for (int g = tid; g < nGts; g += NT) {
        const int b = gt_batch[g];
        float4 box = boxes4[g];
        float gx = box.x * (float)NW, gy = box.y * (float)NH;
        float gw = box.z * (float)NW, gh = box.w * (float)NH;
        int gi = (int)gx, gj = (int)gy;

        float best = -1.0f; int bestn = 0;
#pragma unroll
        for (int a = 0; a < 3; a++) {
            float inter = fminf(gw, awf[a]) * fminf(gh, ahf[a]);
            float uni   = gw * gh + awf[a] * ahf[a] - inter;
            float iou   = inter / uni;
            if (iou > best) { best = iou; bestn = a; }
        }
        const int cell = ((b * NA) * NH + gj) * NW + gi + bestn * NPLANE;
        if (d_owner[cell] == g + 1) {
            const size_t base = (size_t)(b * NCH + bestn * 6) * NPLANE + gj * NW + gi;
            float p0 = out[base];
            float p1 = out[base + NPLANE];
            float p2 = out[base + 2 * NPLANE];
            float p3 = out[base + 3 * NPLANE];
            float p4 = out[base + 4 * NPLANE];

            float tx = gx - floorf(gx);
            float ty = gy - floorf(gy);
            float tw = logf(gw / awf[bestn]);
            float th = logf(gh / ahf[bestn]);

            float xs = sigmoidf_(p0), ys = sigmoidf_(p1);
            float bb = (xs - tx) * (xs - tx) + (ys - ty) * (ys - ty)
                     + (p2 - tw) * (p2 - tw) + (p3 - th) * (p3 - th);
            objsum += (double)(bb + bce_pos(p4));   // OBJ_SCALE = 1
            nobj++;
        }
    }
    redD[tid] = objsum; redI[tid] = nobj;
    __syncthreads();
    for (int k = NT >> 1; k > 0; k >>= 1) {
        if (tid < k) { redD[tid] += redD[tid + k]; redI[tid] += redI[tid + k]; }
        __syncthreads();
    }
    if (tid == 0) { s_obj = redD[0]; s_nobj = redI[0]; }
    __syncthreads();

    // ---------------- Phase C: cleanup (self-cleaning scratch) ----------------
    for (int g = tid; g < nGts; g += NT) {
        const int b = gt_batch[g];
        float4 box = boxes4[g];
        float gw = box.z * (float)NW, gh = box.w * (float)NH;
        int gi = (int)(box.x * (float)NW), gj = (int)(box.y * (float)NH);

        float ious[3]; float best = -1.0f; int bestn = 0;
#pragma unroll
        for (int a = 0; a < 3; a++) {
            float inter = fminf(gw, awf[a]) * fminf(gh, ahf[a]);
            float uni   = gw * gh + awf[a] * ahf[a] - inter;
            float iou   = inter / uni;
            ious[a] = iou;
            if (iou > best) { best = iou; bestn = a; }
        }
        const int cellbase = ((b * NA) * NH + gj) * NW + gi;
#pragma unroll
        for (int a = 0; a < 3; a++) {
            if ((ious[a] > 0.5f) || (a == bestn)) d_clr[cellbase + a * NPLANE] = 0;
        }
        d_owner[cellbase + bestn * NPLANE] = 0;
    }

    // ---------------- Phase D: finalize ----------------
    if (tid == 0) {
        double total  = d_total;
        double n_obj  = (double)(s_nobj  > 0 ? s_nobj : 1);
        int    nno    = NCELL - s_nclr;
        double n_noob = (double)(nno > 0 ? nno : 1);
        double loss = s_obj / n_obj + 100.0 * (total - s_corr) / n_noob;
        d_out[0] = (float)loss;
        d_total = 0.0;   // reset accumulator for next launch
    }
}

extern "C" void kernel_launch(void* const* d_in, const int* in_sizes, int n_in,
                              void* d_out, int out_size) {
    const float* out      = (const float*)d_in[0];
    const int*   gt_batch = (const int*)  d_in[1];
    const float* gt_boxes = (const float*)d_in[2];
    const int*   size_h   = (const int*)  d_in[3];
    const int*   size_w   = (const int*)  d_in[4];
    float* outp = (float*)d_out;
    const int nGts = in_sizes[1];

    // Dense conf-channel BCE sum: 393,216 float4 -> 1536 blocks x 256 threads
    conf_sum_kernel<<<1536, 256>>>(out);
    // Sparse GT phases + finalize in one single-block kernel
    tail_kernel<<<1, 1024>>>(out, gt_batch, gt_boxes, size_h, size_w, outp, nGts);
}

// round 3
// speedup vs baseline: 1.6716x; 1.6716x over previous
#include <cuda_runtime.h>
#include <math.h>

// Problem constants (shapes fixed by the dataset)
#define NB 32
#define NA 3
#define NH 128
#define NW 128
#define NCH (NA * 6)              // 18 channels
#define NPLANE (NH * NW)          // 16384
#define NCELL (NB * NA * NPLANE)  // 1,572,864
#define EPSF 1e-7f
#define DENSE_BLOCKS 1536

// Self-cleaning scratch (zero-initialized at module load; every launch restores zeros)
__device__ int    d_clr[NCELL];    // cleared-cell dedup flags
__device__ int    d_owner[NCELL];  // winning gt index + 1 per obj cell
__device__ double d_total;         // dense noobj-BCE sum over ALL cells
__device__ double d_corr;          // correction sum (noobj terms at cleared cells)
__device__ double d_obj;           // obj BCE + bbox loss sum
__device__ int    d_nclr;          // # distinct cleared cells
__device__ int    d_nobj;          // # distinct obj cells (winners)
__device__ int    d_done;          // block-completion ticket for kernel 2

__constant__ float c_aw[3] = {116.f, 156.f, 373.f};
__constant__ float c_ah[3] = { 90.f, 198.f, 326.f};

// -log(1 - clip(sigmoid(v), eps, 1-eps))   [noobj BCE term]
__device__ __forceinline__ float bce_neg(float v) {
    float s = 1.0f / (1.0f + expf(-v));
    float p = fminf(fmaxf(s, EPSF), 1.0f - EPSF);
    return -logf(1.0f - p);
}
// -log(clip(sigmoid(v), eps, 1-eps))       [obj BCE term]
__device__ __forceinline__ float bce_pos(float v) {
    float s = 1.0f / (1.0f + expf(-v));
    float p = fminf(fmaxf(s, EPSF), 1.0f - EPSF);
    return -logf(p);
}
__device__ __forceinline__ float sigmoidf_(float v) {
    return 1.0f / (1.0f + expf(-v));
}

// Shared helper: anchor IoUs + argmax for one gt box (grid units)
__device__ __forceinline__ int best_anchor(float gw, float gh,
                                           const float* awf, const float* ahf,
                                           float* ious) {
    float best = -1.0f; int bestn = 0;
#pragma unroll
    for (int a = 0; a < 3; a++) {
        float inter = fminf(gw, awf[a]) * fminf(gh, ahf[a]);
        float uni   = gw * gh + awf[a] * ahf[a] - inter;
        float iou   = inter / uni;
        ious[a] = iou;
        if (iou > best) { best = iou; bestn = a; }
    }
    return bestn;
}

// ---------------------------------------------------------------------------
// Kernel 1: blocks [0, DENSE_BLOCKS) — dense sum of -log(1-p) over conf channel.
//           blocks [DENSE_BLOCKS, ...) — Phase A: per-gt dedup/clear + owner max.
// ---------------------------------------------------------------------------
__global__ void fused_dense_phaseA(const float* __restrict__ out,
                                   const int*   __restrict__ gt_batch,
                                   const float* __restrict__ gt_boxes,
                                   const int*   __restrict__ size_h,
                                   const int*   __restrict__ size_w,
                                   int nGts) {
    const int tid = threadIdx.x;

    if (blockIdx.x < DENSE_BLOCKS) {
        // ---------------- dense conf-BCE sum ----------------
        const int idx = blockIdx.x * 256 + tid;            // 0 .. 393215
        const float4* __restrict__ o4 = (const float4*)out;
        const int plane = idx >> 12;                       // 0..95  (b*3 + a)
        const int j     = idx & 4095;
        const int b     = plane / 3;
        const int a     = plane - 3 * b;
        const size_t off = (size_t)(b * NCH + a * 6 + 4) * 4096 + j;
        float4 v = o4[off];
        float s = bce_neg(v.x) + bce_neg(v.y) + bce_neg(v.z) + bce_neg(v.w);

        __shared__ float red[256];
        red[tid] = s;
        __syncthreads();
#pragma unroll
        for (int k = 128; k > 0; k >>= 1) {
            if (tid < k) red[tid] += red[tid + k];
            __syncthreads();
        }
        if (tid == 0) atomicAdd(&d_total, (double)red[0]);
        return;
    }

    // ---------------- Phase A: one gt per thread ----------------
    const float stride_h = (float)((*size_h) / NH);
    const float stride_w = (float)((*size_w) / NW);
    float awf[3], ahf[3];
#pragma unroll
    for (int a = 0; a < 3; a++) { awf[a] = c_aw[a] / stride_w; ahf[a] = c_ah[a] / stride_h; }

    const int g = (blockIdx.x - DENSE_BLOCKS) * 256 + tid;
    double corr = 0.0;
    int nclr = 0;
    if (g < nGts) {
        const int b = gt_batch[g];
        float4 box = ((const float4*)gt_boxes)[g];
        float gx = box.x * (float)NW, gy = box.y * (float)NH;
        float gw = box.z * (float)NW, gh = box.w * (float)NH;
        int gi = (int)gx, gj = (int)gy;

        float ious[3];
        int bestn = best_anchor(gw, gh, awf, ahf, ious);
        const int cellbase = ((b * NA) * NH + gj) * NW + gi;
#pragma unroll
        for (int a = 0; a < 3; a++) {
            bool cleared = (ious[a] > 0.5f) || (a == bestn);
            if (cleared) {
                int cell = cellbase + a * NPLANE;
                if (atomicExch(&d_clr[cell], 1) == 0) {
                    float v = out[(size_t)(b * NCH + a * 6 + 4) * NPLANE + gj * NW + gi];
                    corr += (double)bce_neg(v);
                    nclr++;
                }
            }
        }
        atomicMax(&d_owner[cellbase + bestn * NPLANE], g + 1);
    }

    __shared__ double redD[256];
    __shared__ int    redI[256];
    redD[tid] = corr; redI[tid] = nclr;
    __syncthreads();
#pragma unroll
    for (int k = 128; k > 0; k >>= 1) {
        if (tid < k) { redD[tid] += redD[tid + k]; redI[tid] += redI[tid + k]; }
        __syncthreads();
    }
    if (tid == 0) {
        if (redI[0] > 0) { atomicAdd(&d_corr, redD[0]); atomicAdd(&d_nclr, redI[0]); }
    }
}

// ---------------------------------------------------------------------------
// Kernel 2: Phase B (owner winners -> obj terms) + fused cleanup + finalize.
// One gt per thread; last block (ticket) writes the scalar and resets all
// accumulators, keeping scratch self-cleaning.
// ---------------------------------------------------------------------------
__global__ void phaseB_finalize(const float* __restrict__ out,
                                const int*   __restrict__ gt_batch,
                                const float* __restrict__ gt_boxes,
                                const int*   __restrict__ size_h,
                                const int*   __restrict__ size_w,
                                float* __restrict__ d_out,
                                int nGts) {
    const int tid = threadIdx.x;

    const float stride_h = (float)((*size_h) / NH);
    const float stride_w = (float)((*size_w) / NW);
    float awf[3], ahf[3];
#pragma unroll
    for (int a = 0; a < 3; a++) { awf[a] = c_aw[a] / stride_w; ahf[a] = c_ah[a] / stride_h; }

    const int g = blockIdx.x * 256 + tid;
    double objsum = 0.0;
    int nobj = 0;
    if (g < nGts) {
        const int b = gt_batch[g];
        float4 box = ((const float4*)gt_boxes)[g];
        float gx = box.x * (float)NW, gy = box.y * (float)NH;
        float gw = box.z * (float)NW, gh = box.w * (float)NH;
        int gi = (int)gx, gj = (int)gy;

        float ious[3];
        int bestn = best_anchor(gw, gh, awf, ahf, ious);
        const int cellbase = ((b * NA) * NH + gj) * NW + gi;
        const int cell = cellbase + bestn * NPLANE;

        if (__ldcg(&d_owner[cell]) == g + 1) {
            const size_t base = (size_t)(b * NCH + bestn * 6) * NPLANE + gj * NW + gi;
            float p0 = out[base];
            float p1 = out[base + NPLANE];
            float p2 = out[base + 2 * NPLANE];
            float p3 = out[base + 3 * NPLANE];
            float p4 = out[base + 4 * NPLANE];

            float tx = gx - floorf(gx);
            float ty = gy - floorf(gy);
            float tw = logf(gw / awf[bestn]);
            float th = logf(gh / ahf[bestn]);

            float xs = sigmoidf_(p0), ys = sigmoidf_(p1);
            float bb = (xs - tx) * (xs - tx) + (ys - ty) * (ys - ty)
                     + (p2 - tw) * (p2 - tw) + (p3 - th) * (p3 - th);
            objsum += (double)(bb + bce_pos(p4));   // OBJ_SCALE = 1
            nobj++;
            d_owner[cell] = 0;   // winner cleans; losers read 0 != g+1 -> still correct
        }
        // cleanup dedup flags (write-only here; idempotent zeroing)
#pragma unroll
        for (int a = 0; a < 3; a++) {
            if ((ious[a] > 0.5f) || (a == bestn)) d_clr[cellbase + a * NPLANE] = 0;
        }
    }

    __shared__ double redD[256];
    __shared__ int    redI[256];
    redD[tid] = objsum; redI[tid] = nobj;
    __syncthreads();
#pragma unroll
    for (int k = 128; k > 0; k >>= 1) {
        if (tid < k) { redD[tid] += redD[tid + k]; redI[tid] += redI[tid + k]; }
        __syncthreads();
    }

    if (tid == 0) {
        if (redI[0] > 0) { atomicAdd(&d_obj, redD[0]); atomicAdd(&d_nobj, redI[0]); }
        __threadfence();
        int ticket = atomicAdd(&d_done, 1);
        if (ticket == gridDim.x - 1) {
            // all blocks' accumulator atomics are visible (fence + ticket order)
            double total = d_total;
            double corr  = d_corr;
            double obj   = d_obj;
            int    no    = d_nobj;
            int    ncl   = d_nclr;
            double n_obj  = (double)(no > 0 ? no : 1);
            int    nno    = NCELL - ncl;
            double n_noob = (double)(nno > 0 ? nno : 1);
            d_out[0] = (float)(obj / n_obj + 100.0 * (total - corr) / n_noob);
            // reset accumulators for the next launch (self-cleaning)
            d_total = 0.0; d_corr = 0.0; d_obj = 0.0;
            d_nclr = 0; d_nobj = 0; d_done = 0;
        }
    }
}

extern "C" void kernel_launch(void* const* d_in, const int* in_sizes, int n_in,
                              void* d_out, int out_size) {
    const float* out      = (const float*)d_in[0];
    const int*   gt_batch = (const int*)  d_in[1];
    const float* gt_boxes = (const float*)d_in[2];
    const int*   size_h   = (const int*)  d_in[3];
    const int*   size_w   = (const int*)  d_in[4];
    float* outp = (float*)d_out;
    const int nGts = in_sizes[1];

    const int gtBlocks = (nGts + 255) / 256;
    fused_dense_phaseA<<<DENSE_BLOCKS + gtBlocks, 256>>>(out, gt_batch, gt_boxes,
                                                         size_h, size_w, nGts);
    phaseB_finalize<<<gtBlocks, 256>>>(out, gt_batch, gt_boxes,
                                       size_h, size_w, outp, nGts);
}